// round 12
// baseline (speedup 1.0000x reference)
#include <cuda_runtime.h>
#include <cuda_bf16.h>

// ===================== table parameters =====================
#define TN      4092                  // table entries (TN+4 = 4096 = 128 blocks * 32)
#define T_LO    (-24.0f)              // t = log2(d^2); d in [2^-12, 32]
#define T_HI    (10.0f)
#define HT      ((T_HI - T_LO) / (float)TN)
#define INV_HT  ((float)TN / (T_HI - T_LO))

#define NBUILD  128                   // blocks that build the table
#define NTHREADS 256
#define BJT     4                     // entries per warp in build phase

__device__ float g_Hval[TN + 4];      // H at grid g = e-2, e in [0, TN+3]
__device__ int   g_arrive = 0;        // build-done counter (self-resetting)
__device__ int   g_depart = 0;        // departure counter (self-resetting)

__device__ __forceinline__ float fast_tanh(float x) {
    x = fminf(fmaxf(x, -15.0f), 15.0f);
    float e = __expf(2.0f * x);
    return 1.0f - __fdividef(2.0f, e + 1.0f);
}

__global__ __launch_bounds__(NTHREADS, 4)
void fused_kernel(
    const float* __restrict__ pos,
    const float* __restrict__ W1, const float* __restrict__ b1,
    const float* __restrict__ W2, const float* __restrict__ b2,
    const float* __restrict__ W3, const float* __restrict__ b3,
    float* __restrict__ out, int N)
{
    __shared__ float4 pos4[1024];                       // 16KB
    __shared__ float  h_s[8 * BJT * 128];               // 16KB

    const int tid  = threadIdx.x;
    const int w    = tid >> 5;
    const int lane = tid & 31;
    const int blk  = blockIdx.x;
    const int b    = blk >> 7;          // batch
    const int ig   = blk & 127;         // i-group within batch

    // ---- all blocks: preload pos tile for force phase (hidden behind build) ----
    const float* pos_b = pos + (size_t)b * N * 3;
    for (int idx = tid; idx < N; idx += NTHREADS)
        pos4[idx] = make_float4(pos_b[idx * 3 + 0], pos_b[idx * 3 + 1],
                                pos_b[idx * 3 + 2], 0.0f);

    // =================== PHASE 1: build table (blocks 0..NBUILD-1) ===================
    if (blk < NBUILD) {
        // lane owns k = 4*lane + u
        const float4 w1r0 = ((const float4*)W1)[lane];
        const float4 w1r1 = ((const float4*)(W1 + 128))[lane];
        const float4 w1r2 = ((const float4*)(W1 + 256))[lane];
        const float4 b1v  = ((const float4*)b1)[lane];

        const int ebase = blk * (8 * BJT) + w * BJT;

        float invs[BJT];
        #pragma unroll
        for (int jl = 0; jl < BJT; ++jl) {
            int e = ebase + jl;
            float t  = T_LO + (float)(e - 2) * HT;     // grid g = e-2
            float d  = exp2f(0.5f * t);
            float dc = fmaxf(d, 0.01f);
            float inv = 1.0f / dc;
            invs[jl] = inv;
            float inv2 = inv * inv;

            float4 pre;
            pre.x = fmaf(d, w1r0.x, fmaf(inv, w1r1.x, fmaf(inv2, w1r2.x, b1v.x)));
            pre.y = fmaf(d, w1r0.y, fmaf(inv, w1r1.y, fmaf(inv2, w1r2.y, b1v.y)));
            pre.z = fmaf(d, w1r0.z, fmaf(inv, w1r1.z, fmaf(inv2, w1r2.z, b1v.z)));
            pre.w = fmaf(d, w1r0.w, fmaf(inv, w1r1.w, fmaf(inv2, w1r2.w, b1v.w)));

            float4 h;
            h.x = fast_tanh(pre.x);
            h.y = fast_tanh(pre.y);
            h.z = fast_tanh(pre.z);
            h.w = fast_tanh(pre.w);
            ((float4*)(h_s + (w * BJT + jl) * 128))[lane] = h;
        }
        __syncwarp();

        // layer 2: W2 straight from global (L1/L2 resident), acc[jl] = h[jl] @ W2[:,kslice]
        const float4* W2v = (const float4*)W2;          // row c: W2v[c*32 + lane]
        float4 acc[BJT];
        #pragma unroll
        for (int jl = 0; jl < BJT; ++jl) acc[jl] = make_float4(0.f, 0.f, 0.f, 0.f);

        #pragma unroll 4
        for (int c4 = 0; c4 < 32; ++c4) {
            float4 wv0 = W2v[(c4 * 4 + 0) * 32 + lane];
            float4 wv1 = W2v[(c4 * 4 + 1) * 32 + lane];
            float4 wv2 = W2v[(c4 * 4 + 2) * 32 + lane];
            float4 wv3 = W2v[(c4 * 4 + 3) * 32 + lane];
            #pragma unroll
            for (int jl = 0; jl < BJT; ++jl) {
                float4 hv = ((const float4*)(h_s + (w * BJT + jl) * 128))[c4];
                acc[jl].x = fmaf(hv.x, wv0.x, acc[jl].x);
                acc[jl].y = fmaf(hv.x, wv0.y, acc[jl].y);
                acc[jl].z = fmaf(hv.x, wv0.z, acc[jl].z);
                acc[jl].w = fmaf(hv.x, wv0.w, acc[jl].w);
                acc[jl].x = fmaf(hv.y, wv1.x, acc[jl].x);
                acc[jl].y = fmaf(hv.y, wv1.y, acc[jl].y);
                acc[jl].z = fmaf(hv.y, wv1.z, acc[jl].z);
                acc[jl].w = fmaf(hv.y, wv1.w, acc[jl].w);
                acc[jl].x = fmaf(hv.z, wv2.x, acc[jl].x);
                acc[jl].y = fmaf(hv.z, wv2.y, acc[jl].y);
                acc[jl].z = fmaf(hv.z, wv2.z, acc[jl].z);
                acc[jl].w = fmaf(hv.z, wv2.w, acc[jl].w);
                acc[jl].x = fmaf(hv.w, wv3.x, acc[jl].x);
                acc[jl].y = fmaf(hv.w, wv3.y, acc[jl].y);
                acc[jl].z = fmaf(hv.w, wv3.z, acc[jl].z);
                acc[jl].w = fmaf(hv.w, wv3.w, acc[jl].w);
            }
        }

        // layer 3 + reduce + write H
        const float4 b2v = ((const float4*)b2)[lane];
        const float4 w3v = ((const float4*)W3)[lane];
        const float  b3v = b3[0];

        #pragma unroll
        for (int jl = 0; jl < BJT; ++jl) {
            float h2x = fast_tanh(acc[jl].x + b2v.x);
            float h2y = fast_tanh(acc[jl].y + b2v.y);
            float h2z = fast_tanh(acc[jl].z + b2v.z);
            float h2w = fast_tanh(acc[jl].w + b2v.w);
            float s = fmaf(h2x, w3v.x, fmaf(h2y, w3v.y, fmaf(h2z, w3v.z, h2w * w3v.w)));
            #pragma unroll
            for (int off = 16; off > 0; off >>= 1)
                s += __shfl_xor_sync(0xffffffffu, s, off);
            if (lane == 0)
                g_Hval[ebase + jl] = (s + b3v) * invs[jl];
        }

        __threadfence();
        __syncthreads();                 // all warps' writes done before arrive
        if (tid == 0) atomicAdd(&g_arrive, 1);
    }

    // =================== device-wide barrier ===================
    if (tid == 0) {
        while (atomicAdd(&g_arrive, 0) < NBUILD)
            __nanosleep(64);
    }
    __syncthreads();
    __threadfence();

    // =================== PHASE 2: force (all blocks) ===================
    const int i = ig * 8 + w;            // one row (b,i) per warp
    const float4 pi = pos4[i];

    float fx = 0.0f, fy = 0.0f, fz = 0.0f;

    #pragma unroll 8
    for (int jj = 0; jj < 32; ++jj) {
        int j = jj * 32 + lane;
        float4 pj = pos4[j];
        float dx = pi.x - pj.x;
        float dy = pi.y - pj.y;
        float dz = pi.z - pj.z;
        float s = fmaf(dx, dx, fmaf(dy, dy, dz * dz));
        float t = __log2f(s);                          // s=0 -> -inf -> clamps
        float u = (t - T_LO) * INV_HT;
        u = fminf(fmaxf(u, 0.0f), (float)TN - 1.001f);
        int   k = (int)u;
        float f = u - (float)k;
        float h0 = __ldg(&g_Hval[k + 1]);              // grid k-1
        float h1 = __ldg(&g_Hval[k + 2]);              // grid k
        float h2 = __ldg(&g_Hval[k + 3]);              // grid k+1
        float h3 = __ldg(&g_Hval[k + 4]);              // grid k+2
        // Catmull-Rom
        float c = h1 + 0.5f * f * ((h2 - h0) +
                  f * ((2.0f * h0 - 5.0f * h1 + 4.0f * h2 - h3) +
                  f * (3.0f * (h1 - h2) + (h3 - h0))));
        fx = fmaf(c, dx, fx);
        fy = fmaf(c, dy, fy);
        fz = fmaf(c, dz, fz);
    }

    #pragma unroll
    for (int off = 16; off > 0; off >>= 1) {
        fx += __shfl_xor_sync(0xffffffffu, fx, off);
        fy += __shfl_xor_sync(0xffffffffu, fy, off);
        fz += __shfl_xor_sync(0xffffffffu, fz, off);
    }
    if (lane == 0) {
        float* o = out + ((size_t)b * N + i) * 3;
        o[0] = fx; o[1] = fy; o[2] = fz;
    }

    // =================== counter reset (last block out resets both) ===================
    __syncthreads();
    if (tid == 0) {
        int d = atomicAdd(&g_depart, 1);
        if (d == (int)gridDim.x - 1) {
            g_arrive = 0;
            __threadfence();
            g_depart = 0;
            __threadfence();
        }
    }
}

// ===================== launch =====================
extern "C" void kernel_launch(void* const* d_in, const int* in_sizes, int n_in,
                              void* d_out, int out_size) {
    const float* pos = (const float*)d_in[0];
    const float* W1  = (const float*)d_in[1];
    const float* b1  = (const float*)d_in[2];
    const float* W2  = (const float*)d_in[3];
    const float* b2  = (const float*)d_in[4];
    const float* W3  = (const float*)d_in[5];
    const float* b3  = (const float*)d_in[6];
    float* out = (float*)d_out;

    const int N = 1024;
    const int B = in_sizes[0] / (N * 3);

    fused_kernel<<<B * 128, NTHREADS>>>(pos, W1, b1, W2, b2, W3, b3, out, N);
}

// round 13
// speedup vs baseline: 1.2545x; 1.2545x over previous
#include <cuda_runtime.h>
#include <cuda_bf16.h>

// ===================== table parameters =====================
#define TN      2048                  // table entries
#define T_LO    (-24.0f)              // t = log2(d^2); d in [2^-12, 32]
#define T_HI    (10.0f)
#define HT      ((T_HI - T_LO) / (float)TN)
#define INV_HT  ((float)TN / (T_HI - T_LO))

__device__ float  g_Hval[TN + 4];     // H at grid g = e-2, e in [0, TN+3]
__device__ float4 g_tab4[TN];         // g_tab4[k] = H at grid {k-1, k, k+1, k+2}

__device__ __forceinline__ float fast_tanh(float x) {
    x = fminf(fmaxf(x, -15.0f), 15.0f);
    float e = __expf(2.0f * x);
    return 1.0f - __fdividef(2.0f, e + 1.0f);
}

// ===================== build kernel: 4 warps per entry, c-split =====================
// block = 256 thr = 8 warps = 2 entries; grid = (TN+4)/2 = 1026 blocks
__global__ __launch_bounds__(256)
void build_table_kernel(
    const float* __restrict__ W1, const float* __restrict__ b1,
    const float* __restrict__ W2, const float* __restrict__ b2,
    const float* __restrict__ W3, const float* __restrict__ b3)
{
    __shared__ float part[8 * 128];   // per-warp layer-2 partials (4KB)

    const int tid  = threadIdx.x;
    const int w    = tid >> 5;
    const int lane = tid & 31;
    const int eg   = w >> 2;          // entry within block (0/1)
    const int cs   = w & 3;           // c-slice (32 c's per warp)

    const int e = blockIdx.x * 2 + eg;

    // ---- features (every warp computes its entry's scalars) ----
    float t  = T_LO + (float)(e - 2) * HT;    // grid g = e-2
    float d  = exp2f(0.5f * t);
    float dc = fmaxf(d, 0.01f);
    float inv  = 1.0f / dc;
    float inv2 = inv * inv;

    // ---- layer 1 for this warp's c-slice: c = cs*32 + lane ----
    const int c = cs * 32 + lane;
    float pre = fmaf(d,    W1[c],
                fmaf(inv,  W1[128 + c],
                fmaf(inv2, W1[256 + c], b1[c])));
    float h = fast_tanh(pre);

    // ---- layer 2 partial: acc[k] += h[c] * W2[c][k], k = 4*lane+u ----
    const float4* W2v = (const float4*)W2;    // row c: W2v[c*32 + lane]
    float4 acc = make_float4(0.f, 0.f, 0.f, 0.f);

    #pragma unroll 8
    for (int cc = 0; cc < 32; ++cc) {
        float  hb = __shfl_sync(0xffffffffu, h, cc);
        float4 wv = W2v[(cs * 32 + cc) * 32 + lane];
        acc.x = fmaf(hb, wv.x, acc.x);
        acc.y = fmaf(hb, wv.y, acc.y);
        acc.z = fmaf(hb, wv.z, acc.z);
        acc.w = fmaf(hb, wv.w, acc.w);
    }
    ((float4*)(part + w * 128))[lane] = acc;
    __syncthreads();

    // ---- lead warp of each entry: reduce 4 partials, layer 3, write ----
    if (cs == 0) {
        float4 a0 = ((const float4*)(part + (eg * 4 + 0) * 128))[lane];
        float4 a1 = ((const float4*)(part + (eg * 4 + 1) * 128))[lane];
        float4 a2 = ((const float4*)(part + (eg * 4 + 2) * 128))[lane];
        float4 a3 = ((const float4*)(part + (eg * 4 + 3) * 128))[lane];
        float4 b2v = ((const float4*)b2)[lane];
        float4 w3v = ((const float4*)W3)[lane];

        float h2x = fast_tanh(a0.x + a1.x + a2.x + a3.x + b2v.x);
        float h2y = fast_tanh(a0.y + a1.y + a2.y + a3.y + b2v.y);
        float h2z = fast_tanh(a0.z + a1.z + a2.z + a3.z + b2v.z);
        float h2w = fast_tanh(a0.w + a1.w + a2.w + a3.w + b2v.w);
        float s = fmaf(h2x, w3v.x, fmaf(h2y, w3v.y, fmaf(h2z, w3v.z, h2w * w3v.w)));

        #pragma unroll
        for (int off = 16; off > 0; off >>= 1)
            s += __shfl_xor_sync(0xffffffffu, s, off);

        if (lane == 0)
            g_Hval[e] = (s + b3[0]) * inv;
    }
}

// ===================== pack kernel =====================
__global__ void pack_table_kernel() {
    int k = blockIdx.x * blockDim.x + threadIdx.x;
    if (k < TN)
        g_tab4[k] = make_float4(g_Hval[k + 1], g_Hval[k + 2],
                                g_Hval[k + 3], g_Hval[k + 4]);
}

// ===================== force kernel =====================
__global__ __launch_bounds__(256)
void force_kernel(const float* __restrict__ pos, float* __restrict__ out, int N)
{
    __shared__ float4 pos4[1024];
    const int tid = threadIdx.x;
    const int b   = blockIdx.y;
    const float* pos_b = pos + (size_t)b * N * 3;

    for (int idx = tid; idx < N; idx += 256)
        pos4[idx] = make_float4(pos_b[idx * 3 + 0], pos_b[idx * 3 + 1],
                                pos_b[idx * 3 + 2], 0.0f);
    __syncthreads();

    const int w    = tid >> 5;
    const int lane = tid & 31;
    const int i    = blockIdx.x * 8 + w;     // one i per warp
    const float4 pi = pos4[i];

    float fx = 0.0f, fy = 0.0f, fz = 0.0f;

    #pragma unroll 8
    for (int jj = 0; jj < 32; ++jj) {
        int j = jj * 32 + lane;
        float4 pj = pos4[j];
        float dx = pi.x - pj.x;
        float dy = pi.y - pj.y;
        float dz = pi.z - pj.z;
        float s = fmaf(dx, dx, fmaf(dy, dy, dz * dz));
        float t = __log2f(s);                         // s=0 -> -inf -> clamps
        float u = (t - T_LO) * INV_HT;
        u = fminf(fmaxf(u, 0.0f), (float)TN - 1.001f);
        int   k = (int)u;
        float f = u - (float)k;
        float4 hv = __ldg(&g_tab4[k]);                // H at grid k-1..k+2
        // Catmull-Rom
        float c = hv.y + 0.5f * f * ((hv.z - hv.x) +
                  f * ((2.0f * hv.x - 5.0f * hv.y + 4.0f * hv.z - hv.w) +
                  f * (3.0f * (hv.y - hv.z) + (hv.w - hv.x))));
        fx = fmaf(c, dx, fx);
        fy = fmaf(c, dy, fy);
        fz = fmaf(c, dz, fz);
    }

    #pragma unroll
    for (int off = 16; off > 0; off >>= 1) {
        fx += __shfl_xor_sync(0xffffffffu, fx, off);
        fy += __shfl_xor_sync(0xffffffffu, fy, off);
        fz += __shfl_xor_sync(0xffffffffu, fz, off);
    }
    if (lane == 0) {
        float* o = out + ((size_t)b * N + i) * 3;
        o[0] = fx; o[1] = fy; o[2] = fz;
    }
}

// ===================== launch =====================
extern "C" void kernel_launch(void* const* d_in, const int* in_sizes, int n_in,
                              void* d_out, int out_size) {
    const float* pos = (const float*)d_in[0];
    const float* W1  = (const float*)d_in[1];
    const float* b1  = (const float*)d_in[2];
    const float* W2  = (const float*)d_in[3];
    const float* b2  = (const float*)d_in[4];
    const float* W3  = (const float*)d_in[5];
    const float* b3  = (const float*)d_in[6];
    float* out = (float*)d_out;

    const int N = 1024;
    const int B = in_sizes[0] / (N * 3);

    build_table_kernel<<<(TN + 4) / 2, 256>>>(W1, b1, W2, b2, W3, b3);
    pack_table_kernel<<<TN / 256, 256>>>();
    force_kernel<<<dim3(N / 8, B), 256>>>(pos, out, N);
}

// round 15
// speedup vs baseline: 1.5200x; 1.2117x over previous
#include <cuda_runtime.h>
#include <cuda_bf16.h>

// ===================== table parameters =====================
#define TN      1024                  // table entries
#define T_LO    (-24.0f)              // t = log2(d^2); d in [2^-12, 32]
#define T_HI    (10.0f)
#define HT      ((T_HI - T_LO) / (float)TN)
#define INV_HT  ((float)TN / (T_HI - T_LO))

__device__ float4 g_tab4[TN];         // g_tab4[k] = H at Hval-index {k+1,k+2,k+3,k+4}

__device__ __forceinline__ float fast_tanh(float x) {
    x = fminf(fmaxf(x, -15.0f), 15.0f);
    float e = __expf(2.0f * x);
    return 1.0f - __fdividef(2.0f, e + 1.0f);
}

// ===================== build kernel =====================
// block = 128 thr = 4 warps; each warp owns a 32-c slice for 4 entries.
// grid = (TN+4)/4 = 257 blocks. Each W2 load feeds 4 entries (16 FMA).
__global__ __launch_bounds__(128)
void build_table_kernel(
    const float* __restrict__ W1, const float* __restrict__ b1,
    const float* __restrict__ W2, const float* __restrict__ b2,
    const float* __restrict__ W3, const float* __restrict__ b3)
{
    __shared__ float part[4 * 4 * 128];   // [warp][entry][128] partials (8KB)

    const int tid  = threadIdx.x;
    const int w    = tid >> 5;            // c-slice
    const int lane = tid & 31;
    const int ebase = blockIdx.x * 4;

    // ---- layer-1 weights for this lane's c = w*32 + lane ----
    const int c = w * 32 + lane;
    const float w1a = W1[c];
    const float w1b = W1[128 + c];
    const float w1c = W1[256 + c];
    const float b1c = b1[c];

    // ---- per-entry scalars + layer 1 ----
    float h[4];
    #pragma unroll
    for (int e = 0; e < 4; ++e) {
        float t  = T_LO + (float)(ebase + e - 2) * HT;   // grid g = idx-2
        float d  = exp2f(0.5f * t);
        float dc = fmaxf(d, 0.01f);
        float inv  = 1.0f / dc;
        float inv2 = inv * inv;
        h[e] = fast_tanh(fmaf(d, w1a, fmaf(inv, w1b, fmaf(inv2, w1c, b1c))));
    }

    // ---- layer 2 partials: one W2 load feeds 4 entries ----
    const float4* W2v = (const float4*)W2;     // row r: W2v[r*32 + lane]
    float4 acc[4];
    #pragma unroll
    for (int e = 0; e < 4; ++e) acc[e] = make_float4(0.f, 0.f, 0.f, 0.f);

    #pragma unroll 8
    for (int cc = 0; cc < 32; ++cc) {
        float4 wv = W2v[(w * 32 + cc) * 32 + lane];
        #pragma unroll
        for (int e = 0; e < 4; ++e) {
            float hb = __shfl_sync(0xffffffffu, h[e], cc);
            acc[e].x = fmaf(hb, wv.x, acc[e].x);
            acc[e].y = fmaf(hb, wv.y, acc[e].y);
            acc[e].z = fmaf(hb, wv.z, acc[e].z);
            acc[e].w = fmaf(hb, wv.w, acc[e].w);
        }
    }
    #pragma unroll
    for (int e = 0; e < 4; ++e)
        ((float4*)(part + (w * 4 + e) * 128))[lane] = acc[e];
    __syncthreads();

    // ---- warp w reduces entry w across the 4 c-slices, layer 3, scatter ----
    {
        const int e = w;                       // entry this warp finalizes
        float4 a0 = ((const float4*)(part + (0 * 4 + e) * 128))[lane];
        float4 a1 = ((const float4*)(part + (1 * 4 + e) * 128))[lane];
        float4 a2 = ((const float4*)(part + (2 * 4 + e) * 128))[lane];
        float4 a3 = ((const float4*)(part + (3 * 4 + e) * 128))[lane];
        float4 b2v = ((const float4*)b2)[lane];
        float4 w3v = ((const float4*)W3)[lane];

        float h2x = fast_tanh(a0.x + a1.x + a2.x + a3.x + b2v.x);
        float h2y = fast_tanh(a0.y + a1.y + a2.y + a3.y + b2v.y);
        float h2z = fast_tanh(a0.z + a1.z + a2.z + a3.z + b2v.z);
        float h2w = fast_tanh(a0.w + a1.w + a2.w + a3.w + b2v.w);
        float s = fmaf(h2x, w3v.x, fmaf(h2y, w3v.y, fmaf(h2z, w3v.z, h2w * w3v.w)));

        #pragma unroll
        for (int off = 16; off > 0; off >>= 1)
            s += __shfl_xor_sync(0xffffffffu, s, off);

        if (lane == 0) {
            const int ei = ebase + e;                    // Hval index
            float t  = T_LO + (float)(ei - 2) * HT;
            float d  = exp2f(0.5f * t);
            float inv = 1.0f / fmaxf(d, 0.01f);
            float H = (s + b3[0]) * inv;
            // scatter into tab4 component slots: tab4[k].{x,y,z,w} = Hval[k+1..k+4]
            float* tabf = (float*)g_tab4;
            int k;
            k = ei - 1; if (k >= 0 && k < TN) tabf[k * 4 + 0] = H;
            k = ei - 2; if (k >= 0 && k < TN) tabf[k * 4 + 1] = H;
            k = ei - 3; if (k >= 0 && k < TN) tabf[k * 4 + 2] = H;
            k = ei - 4; if (k >= 0 && k < TN) tabf[k * 4 + 3] = H;
        }
    }
}

// ===================== force kernel (table in shared) =====================
__global__ __launch_bounds__(256)
void force_kernel(const float* __restrict__ pos, float* __restrict__ out, int N)
{
    __shared__ float4 pos4[1024];      // 16KB
    __shared__ float4 tab[TN];         // 16KB
    const int tid = threadIdx.x;
    const int b   = blockIdx.y;
    const float* pos_b = pos + (size_t)b * N * 3;

    for (int idx = tid; idx < N; idx += 256)
        pos4[idx] = make_float4(pos_b[idx * 3 + 0], pos_b[idx * 3 + 1],
                                pos_b[idx * 3 + 2], 0.0f);
    for (int idx = tid; idx < TN; idx += 256)
        tab[idx] = g_tab4[idx];
    __syncthreads();

    const int w    = tid >> 5;
    const int lane = tid & 31;
    const int i    = blockIdx.x * 8 + w;     // one i per warp
    const float4 pi = pos4[i];

    float fx = 0.0f, fy = 0.0f, fz = 0.0f;

    #pragma unroll 8
    for (int jj = 0; jj < 32; ++jj) {
        int j = jj * 32 + lane;
        float4 pj = pos4[j];
        float dx = pi.x - pj.x;
        float dy = pi.y - pj.y;
        float dz = pi.z - pj.z;
        float s = fmaf(dx, dx, fmaf(dy, dy, dz * dz));
        float t = __log2f(s);                         // s=0 -> -inf -> clamps
        float u = (t - T_LO) * INV_HT;
        u = fminf(fmaxf(u, 0.0f), (float)TN - 1.001f);
        int   k = (int)u;
        float f = u - (float)k;
        float4 hv = tab[k];                           // LDS.128 gather
        // Catmull-Rom
        float c = hv.y + 0.5f * f * ((hv.z - hv.x) +
                  f * ((2.0f * hv.x - 5.0f * hv.y + 4.0f * hv.z - hv.w) +
                  f * (3.0f * (hv.y - hv.z) + (hv.w - hv.x))));
        fx = fmaf(c, dx, fx);
        fy = fmaf(c, dy, fy);
        fz = fmaf(c, dz, fz);
    }

    #pragma unroll
    for (int off = 16; off > 0; off >>= 1) {
        fx += __shfl_xor_sync(0xffffffffu, fx, off);
        fy += __shfl_xor_sync(0xffffffffu, fy, off);
        fz += __shfl_xor_sync(0xffffffffu, fz, off);
    }
    if (lane == 0) {
        float* o = out + ((size_t)b * N + i) * 3;
        o[0] = fx; o[1] = fy; o[2] = fz;
    }
}

// ===================== launch =====================
extern "C" void kernel_launch(void* const* d_in, const int* in_sizes, int n_in,
                              void* d_out, int out_size) {
    const float* pos = (const float*)d_in[0];
    const float* W1  = (const float*)d_in[1];
    const float* b1  = (const float*)d_in[2];
    const float* W2  = (const float*)d_in[3];
    const float* b2  = (const float*)d_in[4];
    const float* W3  = (const float*)d_in[5];
    const float* b3  = (const float*)d_in[6];
    float* out = (float*)d_out;

    const int N = 1024;
    const int B = in_sizes[0] / (N * 3);

    build_table_kernel<<<(TN + 4) / 4, 128>>>(W1, b1, W2, b2, W3, b3);
    force_kernel<<<dim3(N / 8, B), 256>>>(pos, out, N);
}

// round 16
// speedup vs baseline: 1.5431x; 1.0152x over previous
#include <cuda_runtime.h>
#include <cuda_bf16.h>

// ===================== table parameters =====================
#define TN      1024                  // table entries
#define T_LO    (-24.0f)              // t = log2(d^2); d in [2^-12, 32]
#define T_HI    (10.0f)
#define HT      ((T_HI - T_LO) / (float)TN)
#define INV_HT  ((float)TN / (T_HI - T_LO))

__device__ float4 g_tab4[TN];         // g_tab4[k] = H at Hval-index {k+1,k+2,k+3,k+4}

__device__ __forceinline__ float fast_tanh(float x) {
    x = fminf(fmaxf(x, -15.0f), 15.0f);
    float e = __expf(2.0f * x);
    return 1.0f - __fdividef(2.0f, e + 1.0f);
}

// ===================== build kernel =====================
// block = 128 thr = 4 warps; each warp owns a 32-c slice for 4 entries.
// grid = (TN+4)/4 = 257 blocks. Each W2 load feeds 4 entries (16 FMA).
__global__ __launch_bounds__(128)
void build_table_kernel(
    const float* __restrict__ W1, const float* __restrict__ b1,
    const float* __restrict__ W2, const float* __restrict__ b2,
    const float* __restrict__ W3, const float* __restrict__ b3)
{
    __shared__ float part[4 * 4 * 128];   // [warp][entry][128] partials (8KB)

    const int tid  = threadIdx.x;
    const int w    = tid >> 5;            // c-slice
    const int lane = tid & 31;
    const int ebase = blockIdx.x * 4;

    // ---- layer-1 weights for this lane's c = w*32 + lane ----
    const int c = w * 32 + lane;
    const float w1a = W1[c];
    const float w1b = W1[128 + c];
    const float w1c = W1[256 + c];
    const float b1c = b1[c];

    // ---- per-entry scalars + layer 1 ----
    float h[4];
    #pragma unroll
    for (int e = 0; e < 4; ++e) {
        float t  = T_LO + (float)(ebase + e - 2) * HT;   // grid g = idx-2
        float d  = exp2f(0.5f * t);
        float dc = fmaxf(d, 0.01f);
        float inv  = 1.0f / dc;
        float inv2 = inv * inv;
        h[e] = fast_tanh(fmaf(d, w1a, fmaf(inv, w1b, fmaf(inv2, w1c, b1c))));
    }

    // ---- layer 2 partials: one W2 load feeds 4 entries ----
    const float4* W2v = (const float4*)W2;     // row r: W2v[r*32 + lane]
    float4 acc[4];
    #pragma unroll
    for (int e = 0; e < 4; ++e) acc[e] = make_float4(0.f, 0.f, 0.f, 0.f);

    #pragma unroll 8
    for (int cc = 0; cc < 32; ++cc) {
        float4 wv = W2v[(w * 32 + cc) * 32 + lane];
        #pragma unroll
        for (int e = 0; e < 4; ++e) {
            float hb = __shfl_sync(0xffffffffu, h[e], cc);
            acc[e].x = fmaf(hb, wv.x, acc[e].x);
            acc[e].y = fmaf(hb, wv.y, acc[e].y);
            acc[e].z = fmaf(hb, wv.z, acc[e].z);
            acc[e].w = fmaf(hb, wv.w, acc[e].w);
        }
    }
    #pragma unroll
    for (int e = 0; e < 4; ++e)
        ((float4*)(part + (w * 4 + e) * 128))[lane] = acc[e];
    __syncthreads();

    // ---- warp w reduces entry w across the 4 c-slices, layer 3, scatter ----
    {
        const int e = w;                       // entry this warp finalizes
        float4 a0 = ((const float4*)(part + (0 * 4 + e) * 128))[lane];
        float4 a1 = ((const float4*)(part + (1 * 4 + e) * 128))[lane];
        float4 a2 = ((const float4*)(part + (2 * 4 + e) * 128))[lane];
        float4 a3 = ((const float4*)(part + (3 * 4 + e) * 128))[lane];
        float4 b2v = ((const float4*)b2)[lane];
        float4 w3v = ((const float4*)W3)[lane];

        float h2x = fast_tanh(a0.x + a1.x + a2.x + a3.x + b2v.x);
        float h2y = fast_tanh(a0.y + a1.y + a2.y + a3.y + b2v.y);
        float h2z = fast_tanh(a0.z + a1.z + a2.z + a3.z + b2v.z);
        float h2w = fast_tanh(a0.w + a1.w + a2.w + a3.w + b2v.w);
        float s = fmaf(h2x, w3v.x, fmaf(h2y, w3v.y, fmaf(h2z, w3v.z, h2w * w3v.w)));

        #pragma unroll
        for (int off = 16; off > 0; off >>= 1)
            s += __shfl_xor_sync(0xffffffffu, s, off);

        if (lane == 0) {
            const int ei = ebase + e;                    // Hval index
            float t  = T_LO + (float)(ei - 2) * HT;
            float d  = exp2f(0.5f * t);
            float inv = 1.0f / fmaxf(d, 0.01f);
            float H = (s + b3[0]) * inv;
            // scatter into tab4 component slots: tab4[k].{x,y,z,w} = Hval[k+1..k+4]
            float* tabf = (float*)g_tab4;
            int k;
            k = ei - 1; if (k >= 0 && k < TN) tabf[k * 4 + 0] = H;
            k = ei - 2; if (k >= 0 && k < TN) tabf[k * 4 + 1] = H;
            k = ei - 3; if (k >= 0 && k < TN) tabf[k * 4 + 2] = H;
            k = ei - 4; if (k >= 0 && k < TN) tabf[k * 4 + 3] = H;
        }
    }
}

// ===================== force kernel (table in shared) =====================
__global__ __launch_bounds__(256)
void force_kernel(const float* __restrict__ pos, float* __restrict__ out, int N)
{
    __shared__ float4 pos4[1024];      // 16KB
    __shared__ float4 tab[TN];         // 16KB
    const int tid = threadIdx.x;
    const int b   = blockIdx.y;
    const float* pos_b = pos + (size_t)b * N * 3;

    for (int idx = tid; idx < N; idx += 256)
        pos4[idx] = make_float4(pos_b[idx * 3 + 0], pos_b[idx * 3 + 1],
                                pos_b[idx * 3 + 2], 0.0f);
    for (int idx = tid; idx < TN; idx += 256)
        tab[idx] = g_tab4[idx];
    __syncthreads();

    const int w    = tid >> 5;
    const int lane = tid & 31;
    const int i    = blockIdx.x * 8 + w;     // one i per warp
    const float4 pi = pos4[i];

    float fx = 0.0f, fy = 0.0f, fz = 0.0f;

    #pragma unroll 8
    for (int jj = 0; jj < 32; ++jj) {
        int j = jj * 32 + lane;
        float4 pj = pos4[j];
        float dx = pi.x - pj.x;
        float dy = pi.y - pj.y;
        float dz = pi.z - pj.z;
        float s = fmaf(dx, dx, fmaf(dy, dy, dz * dz));
        float t = __log2f(s);                         // s=0 -> -inf -> clamps
        float u = (t - T_LO) * INV_HT;
        u = fminf(fmaxf(u, 0.0f), (float)TN - 1.001f);
        int   k = (int)u;
        float f = u - (float)k;
        float4 hv = tab[k];                           // LDS.128 gather
        // Catmull-Rom
        float c = hv.y + 0.5f * f * ((hv.z - hv.x) +
                  f * ((2.0f * hv.x - 5.0f * hv.y + 4.0f * hv.z - hv.w) +
                  f * (3.0f * (hv.y - hv.z) + (hv.w - hv.x))));
        fx = fmaf(c, dx, fx);
        fy = fmaf(c, dy, fy);
        fz = fmaf(c, dz, fz);
    }

    #pragma unroll
    for (int off = 16; off > 0; off >>= 1) {
        fx += __shfl_xor_sync(0xffffffffu, fx, off);
        fy += __shfl_xor_sync(0xffffffffu, fy, off);
        fz += __shfl_xor_sync(0xffffffffu, fz, off);
    }
    if (lane == 0) {
        float* o = out + ((size_t)b * N + i) * 3;
        o[0] = fx; o[1] = fy; o[2] = fz;
    }
}

// ===================== launch =====================
extern "C" void kernel_launch(void* const* d_in, const int* in_sizes, int n_in,
                              void* d_out, int out_size) {
    const float* pos = (const float*)d_in[0];
    const float* W1  = (const float*)d_in[1];
    const float* b1  = (const float*)d_in[2];
    const float* W2  = (const float*)d_in[3];
    const float* b2  = (const float*)d_in[4];
    const float* W3  = (const float*)d_in[5];
    const float* b3  = (const float*)d_in[6];
    float* out = (float*)d_out;

    const int N = 1024;
    const int B = in_sizes[0] / (N * 3);

    build_table_kernel<<<(TN + 4) / 4, 128>>>(W1, b1, W2, b2, W3, b3);
    force_kernel<<<dim3(N / 8, B), 256>>>(pos, out, N);
}